// round 8
// baseline (speedup 1.0000x reference)
#include <cuda_runtime.h>

#define NN 100000
#define NE 800000
#define IC 96
#define OC 64
#define TNODE 32          // nodes per GEMM block
#define CHUNK 1024        // scan chunk
#define NB ((NN + CHUNK - 1) / CHUNK)   // 98

// ---- scratch (static device globals; no allocation allowed) ----
// Referenced only from device code; never passed as kernel arguments.
__device__ int   g_is64;               // 1 if edge_index is int64, else int32
__device__ float g_dinv[NN];
__device__ int   g_cnt[NN];
__device__ int   g_rowstart[NN];
__device__ int   g_cursor[NN];
__device__ int   g_csum[128];
__device__ int   g_ctop[128];
__device__ int   g_src[NE];            // CSR-by-destination: source node per slot
__device__ __align__(16) float g_w[NE];        // per-edge norm dinv[r]*dinv[c]
__device__ __align__(16) float g_A[NN * OC];   // h = x W^T, hop-2 source
__device__ __align__(16) float g_B[NN * OC];   // hop-1 result

// ---------------------------------------------------------------- edge fetch helper
// int32 layout: r=p32[e],      c=p32[NE+e]
// int64 layout: r=p64[e] low,  c=p64[NE+e] low  (values < 2^31)
__device__ __forceinline__ void load_edge(const int* p32, int e, int& r, int& c) {
    if (g_is64) {
        r = p32[2 * e];
        c = p32[2 * (NE + e)];
    } else {
        r = p32[e];
        c = p32[NE + e];
    }
}

// ---------------------------------------------------------------- dtype detect + init
__global__ void k_detect(const int* __restrict__ ei32) {
    if (blockIdx.x == 0 && threadIdx.x == 0) {
        int nz = 0;
        for (int i = 0; i < 64; i++) nz |= ei32[2 * i + 1];
        g_is64 = (nz == 0) ? 1 : 0;   // odd int32 words all zero => int64 data
    }
}

__global__ void k_init() {
    int i = blockIdx.x * blockDim.x + threadIdx.x;
    if (i < NN) g_cnt[i] = 0;
}

// ---------------------------------------------------------------- count in-degree (edges only)
__global__ void k_count(const int* __restrict__ ei32) {
    int e = blockIdx.x * blockDim.x + threadIdx.x;
    if (e < NE) {
        int r, c;
        load_edge(ei32, e, r, c);
        if ((unsigned)c < NN) atomicAdd(&g_cnt[c], 1);
    }
}

// ---------------------------------------------------------------- scan (1/3): per-chunk exclusive scan
__global__ void k_scan_local() {
    __shared__ int s[256];
    int t = threadIdx.x, blk = blockIdx.x;
    int base = blk * CHUNK + t * 4;
    int v0 = (base + 0 < NN) ? g_cnt[base + 0] : 0;
    int v1 = (base + 1 < NN) ? g_cnt[base + 1] : 0;
    int v2 = (base + 2 < NN) ? g_cnt[base + 2] : 0;
    int v3 = (base + 3 < NN) ? g_cnt[base + 3] : 0;
    int sum = v0 + v1 + v2 + v3;
    s[t] = sum;
    __syncthreads();
    for (int off = 1; off < 256; off <<= 1) {
        int add = (t >= off) ? s[t - off] : 0;
        __syncthreads();
        s[t] += add;
        __syncthreads();
    }
    int excl = s[t] - sum;
    if (base + 0 < NN) g_rowstart[base + 0] = excl;
    if (base + 1 < NN) g_rowstart[base + 1] = excl + v0;
    if (base + 2 < NN) g_rowstart[base + 2] = excl + v0 + v1;
    if (base + 3 < NN) g_rowstart[base + 3] = excl + v0 + v1 + v2;
    if (t == 255) g_csum[blk] = s[255];
}

// ---------------------------------------------------------------- scan (2/3): chunk totals (98, serial)
__global__ void k_scan_tops() {
    int run = 0;
    for (int b = 0; b < NB; b++) { g_ctop[b] = run; run += g_csum[b]; }
}

// ---------------------------------------------------------------- scan (3/3): finalize rowstart/cursor/dinv
__global__ void k_finalize() {
    int i = blockIdx.x * blockDim.x + threadIdx.x;
    if (i < NN) {
        int rs = g_rowstart[i] + g_ctop[i >> 10];
        g_rowstart[i] = rs;
        g_cursor[i]   = rs;
        g_dinv[i]     = rsqrtf((float)g_cnt[i] + 1.0f);   // +1 = self loop
    }
}

// ---------------------------------------------------------------- CSR fill + edge weights
__global__ void k_fill(const int* __restrict__ ei32) {
    int e = blockIdx.x * blockDim.x + threadIdx.x;
    if (e < NE) {
        int r, c;
        load_edge(ei32, e, r, c);
        if ((unsigned)r < NN && (unsigned)c < NN) {
            int pos = atomicAdd(&g_cursor[c], 1);
            g_src[pos] = r;
            g_w[pos]   = g_dinv[r] * g_dinv[c];
        }
    }
}

// ---------------------------------------------------------------- GEMM: g_A = x W^T
// Block tile: 32 nodes x 64 oc, 256 threads, each thread 2 nodes x 4 oc.
__global__ void k_gemm(const float* __restrict__ x, const float* __restrict__ W) {
    __shared__ float Ws[IC][OC + 4];      // [96][68] padded
    __shared__ float xs[TNODE][IC + 4];   // [32][100] padded
    int tid = threadIdx.x;
    int b0  = blockIdx.x * TNODE;

    for (int i = tid; i < OC * IC; i += 256) {      // W[oc][k] -> Ws[k][oc]
        int oc = i / IC, k = i % IC;
        Ws[k][oc] = W[i];
    }
    for (int i = tid; i < TNODE * IC; i += 256) {
        int n = i / IC, k = i % IC;
        int gn = b0 + n;
        xs[n][k] = (gn < NN) ? x[(size_t)gn * IC + k] : 0.0f;
    }
    __syncthreads();

    int ocq = (tid & 15) * 4;     // oc quad base
    int nq  = (tid >> 4) * 2;     // node pair base
    float a00 = 0, a01 = 0, a02 = 0, a03 = 0;
    float a10 = 0, a11 = 0, a12 = 0, a13 = 0;

    #pragma unroll
    for (int k = 0; k < IC; k++) {
        float4 w = *(const float4*)&Ws[k][ocq];
        float x0 = xs[nq][k], x1 = xs[nq + 1][k];
        a00 += x0 * w.x; a01 += x0 * w.y; a02 += x0 * w.z; a03 += x0 * w.w;
        a10 += x1 * w.x; a11 += x1 * w.y; a12 += x1 * w.z; a13 += x1 * w.w;
    }

    int gn0 = b0 + nq, gn1 = gn0 + 1;
    if (gn0 < NN) *(float4*)&g_A[(size_t)gn0 * OC + ocq] = make_float4(a00, a01, a02, a03);
    if (gn1 < NN) *(float4*)&g_A[(size_t)gn1 * OC + ocq] = make_float4(a10, a11, a12, a13);
}

// ---------------------------------------------------------------- gather hops: one warp per destination
// D[d] = dinv[d]^2 * S[d] + sum_{e: col=d} w_e * S[src_e]
// HOP2=false: S=g_A, D=g_B (internal). HOP2=true: S=g_B, D=out with bias+sigmoid.
template <bool HOP2>
__global__ void k_gather(float* __restrict__ out, const float* __restrict__ bias) {
    int gw = (blockIdx.x * blockDim.x + threadIdx.x) >> 5;
    if (gw >= NN) return;
    int lane = threadIdx.x & 31;

    const float2* Sp = (const float2*)(HOP2 ? g_B : g_A);
    float dd = g_dinv[gw]; dd *= dd;
    float2 acc = Sp[(size_t)gw * 32 + lane];
    acc.x *= dd; acc.y *= dd;

    int start = g_rowstart[gw];
    int end   = start + g_cnt[gw];
    #pragma unroll 4
    for (int j = start; j < end; j++) {
        int   s = g_src[j];
        float w = g_w[j];
        float2 v = Sp[(size_t)s * 32 + lane];
        acc.x += w * v.x;
        acc.y += w * v.y;
    }

    if (HOP2) {
        float2 b = ((const float2*)bias)[lane];
        acc.x = 1.0f / (1.0f + __expf(-(acc.x + b.x)));
        acc.y = 1.0f / (1.0f + __expf(-(acc.y + b.y)));
        ((float2*)out)[(size_t)gw * 32 + lane] = acc;
    } else {
        ((float2*)g_B)[(size_t)gw * 32 + lane] = acc;
    }
}

// ---------------------------------------------------------------- launch
extern "C" void kernel_launch(void* const* d_in, const int* in_sizes, int n_in,
                              void* d_out, int out_size) {
    const float* x    = (const float*)d_in[0];
    const int*   ei32 = (const int*)d_in[1];   // raw words; dtype detected on device
    const float* W    = (const float*)d_in[2];
    const float* b    = (const float*)d_in[3];
    float*       out  = (float*)d_out;

    k_detect    <<<1, 32>>>(ei32);
    k_init      <<<(NN + 255) / 256, 256>>>();
    k_count     <<<(NE + 255) / 256, 256>>>(ei32);
    k_scan_local<<<NB, 256>>>();
    k_scan_tops <<<1, 1>>>();
    k_finalize  <<<(NN + 255) / 256, 256>>>();
    k_fill      <<<(NE + 255) / 256, 256>>>(ei32);

    k_gemm      <<<(NN + TNODE - 1) / TNODE, 256>>>(x, W);

    // hop 1: g_B = P * g_A
    k_gather<false><<<(NN * 32 + 255) / 256, 256>>>(nullptr, nullptr);
    // hop 2 + bias + sigmoid: out = sigmoid(P * g_B + b)
    k_gather<true> <<<(NN * 32 + 255) / 256, 256>>>(out, b);
}

// round 9
// speedup vs baseline: 1.0631x; 1.0631x over previous
#include <cuda_runtime.h>

#define NN 100000
#define NE 800000
#define IC 96
#define OC 64
#define TNODE 32          // nodes per GEMM block
#define CHUNK 1024        // scan chunk
#define NB ((NN + CHUNK - 1) / CHUNK)   // 98

// ---- scratch (static device globals; no allocation allowed) ----
// Referenced only from device code; never passed as kernel arguments.
__device__ int   g_is64;               // 1 if edge_index is int64, else int32
__device__ float g_dinv[NN];
__device__ int   g_cnt[NN];
__device__ int   g_rowstart[NN];
__device__ int   g_cursor[NN];
__device__ int   g_csum[128];
__device__ int   g_ctop[128];
__device__ __align__(16) int2  g_sw[NE];       // CSR-by-dest: (src, weight-bits) per slot
__device__ __align__(16) float g_A[NN * OC];   // h = x W^T, hop-1 source
__device__ __align__(16) float g_B[NN * OC];   // hop-1 result / hop-2 source

// ---------------------------------------------------------------- edge fetch helper
// int32 layout: r=p32[e],      c=p32[NE+e]
// int64 layout: r=p64[e] low,  c=p64[NE+e] low  (values < 2^31)
__device__ __forceinline__ void load_edge(const int* p32, int e, int& r, int& c) {
    if (g_is64) {
        r = p32[2 * e];
        c = p32[2 * (NE + e)];
    } else {
        r = p32[e];
        c = p32[NE + e];
    }
}

// ---------------------------------------------------------------- init + dtype detect (fused)
__global__ void k_init(const int* __restrict__ ei32) {
    int i = blockIdx.x * blockDim.x + threadIdx.x;
    if (i < NN) g_cnt[i] = 0;
    if (i == 0) {
        int nz = 0;
        #pragma unroll 8
        for (int k = 0; k < 64; k++) nz |= ei32[2 * k + 1];
        g_is64 = (nz == 0) ? 1 : 0;   // odd int32 words all zero => int64 data
    }
}

// ---------------------------------------------------------------- count in-degree (edges only)
__global__ void k_count(const int* __restrict__ ei32) {
    int e = blockIdx.x * blockDim.x + threadIdx.x;
    if (e < NE) {
        int r, c;
        load_edge(ei32, e, r, c);
        if ((unsigned)c < NN) atomicAdd(&g_cnt[c], 1);
    }
}

// ---------------------------------------------------------------- scan (1/3): per-chunk exclusive scan
__global__ void k_scan_local() {
    __shared__ int s[256];
    int t = threadIdx.x, blk = blockIdx.x;
    int base = blk * CHUNK + t * 4;
    int v0 = (base + 0 < NN) ? g_cnt[base + 0] : 0;
    int v1 = (base + 1 < NN) ? g_cnt[base + 1] : 0;
    int v2 = (base + 2 < NN) ? g_cnt[base + 2] : 0;
    int v3 = (base + 3 < NN) ? g_cnt[base + 3] : 0;
    int sum = v0 + v1 + v2 + v3;
    s[t] = sum;
    __syncthreads();
    for (int off = 1; off < 256; off <<= 1) {
        int add = (t >= off) ? s[t - off] : 0;
        __syncthreads();
        s[t] += add;
        __syncthreads();
    }
    int excl = s[t] - sum;
    if (base + 0 < NN) g_rowstart[base + 0] = excl;
    if (base + 1 < NN) g_rowstart[base + 1] = excl + v0;
    if (base + 2 < NN) g_rowstart[base + 2] = excl + v0 + v1;
    if (base + 3 < NN) g_rowstart[base + 3] = excl + v0 + v1 + v2;
    if (t == 255) g_csum[blk] = s[255];
}

// ---------------------------------------------------------------- scan (2/3): chunk totals (parallel, 1 block)
__global__ void k_scan_tops() {
    __shared__ int s[128];
    int t = threadIdx.x;
    int v = (t < NB) ? g_csum[t] : 0;
    s[t] = v;
    __syncthreads();
    for (int off = 1; off < 128; off <<= 1) {
        int add = (t >= off) ? s[t - off] : 0;
        __syncthreads();
        s[t] += add;
        __syncthreads();
    }
    if (t < NB) g_ctop[t] = s[t] - v;   // exclusive
}

// ---------------------------------------------------------------- scan (3/3): finalize rowstart/cursor/dinv
__global__ void k_finalize() {
    int i = blockIdx.x * blockDim.x + threadIdx.x;
    if (i < NN) {
        int rs = g_rowstart[i] + g_ctop[i >> 10];
        g_rowstart[i] = rs;
        g_cursor[i]   = rs;
        g_dinv[i]     = rsqrtf((float)g_cnt[i] + 1.0f);   // +1 = self loop
    }
}

// ---------------------------------------------------------------- CSR fill: packed (src, weight)
__global__ void k_fill(const int* __restrict__ ei32) {
    int e = blockIdx.x * blockDim.x + threadIdx.x;
    if (e < NE) {
        int r, c;
        load_edge(ei32, e, r, c);
        if ((unsigned)r < NN && (unsigned)c < NN) {
            int pos = atomicAdd(&g_cursor[c], 1);
            float w = g_dinv[r] * g_dinv[c];
            g_sw[pos] = make_int2(r, __float_as_int(w));
        }
    }
}

// ---------------------------------------------------------------- GEMM: g_A = x W^T
// Block tile: 32 nodes x 64 oc, 256 threads, each thread 2 nodes x 4 oc.
__global__ void k_gemm(const float* __restrict__ x, const float* __restrict__ W) {
    __shared__ float Ws[IC][OC + 4];      // [96][68] padded
    __shared__ float xs[TNODE][IC + 4];   // [32][100] padded
    int tid = threadIdx.x;
    int b0  = blockIdx.x * TNODE;

    for (int i = tid; i < OC * IC; i += 256) {      // W[oc][k] -> Ws[k][oc]
        int oc = i / IC, k = i % IC;
        Ws[k][oc] = W[i];
    }
    for (int i = tid; i < TNODE * IC; i += 256) {
        int n = i / IC, k = i % IC;
        int gn = b0 + n;
        xs[n][k] = (gn < NN) ? x[(size_t)gn * IC + k] : 0.0f;
    }
    __syncthreads();

    int ocq = (tid & 15) * 4;     // oc quad base
    int nq  = (tid >> 4) * 2;     // node pair base
    float a00 = 0, a01 = 0, a02 = 0, a03 = 0;
    float a10 = 0, a11 = 0, a12 = 0, a13 = 0;

    #pragma unroll
    for (int k = 0; k < IC; k++) {
        float4 w = *(const float4*)&Ws[k][ocq];
        float x0 = xs[nq][k], x1 = xs[nq + 1][k];
        a00 += x0 * w.x; a01 += x0 * w.y; a02 += x0 * w.z; a03 += x0 * w.w;
        a10 += x1 * w.x; a11 += x1 * w.y; a12 += x1 * w.z; a13 += x1 * w.w;
    }

    int gn0 = b0 + nq, gn1 = gn0 + 1;
    if (gn0 < NN) *(float4*)&g_A[(size_t)gn0 * OC + ocq] = make_float4(a00, a01, a02, a03);
    if (gn1 < NN) *(float4*)&g_A[(size_t)gn1 * OC + ocq] = make_float4(a10, a11, a12, a13);
}

// ---------------------------------------------------------------- gather hops
// 2 nodes per warp: half-warp (16 lanes x float4 = 256B row) per node.
// Each warp instruction touches 2 source rows (512B) => 2 independent
// dependent-chains per warp; unroll-2 gives MLP ~4.
// D[d] = dinv[d]^2 * S[d] + sum_{e: col=d} w_e * S[src_e]
// HOP2=false: S=g_A, D=g_B. HOP2=true: S=g_B, D=out with bias+sigmoid.
template <bool HOP2>
__global__ void k_gather(float* __restrict__ out, const float* __restrict__ bias) {
    int warp = (blockIdx.x * blockDim.x + threadIdx.x) >> 5;
    int node = (warp << 1) | ((threadIdx.x >> 4) & 1);
    if (node >= NN) return;
    int l = threadIdx.x & 15;

    const float4* __restrict__ Sp = (const float4*)(HOP2 ? g_B : g_A);
    float dd = g_dinv[node]; dd *= dd;
    float4 a = Sp[(size_t)node * 16 + l];
    float ax = a.x * dd, ay = a.y * dd, az = a.z * dd, aw = a.w * dd;

    int st  = g_rowstart[node];
    int cnt = g_cnt[node];
    int j = 0;
    for (; j + 2 <= cnt; j += 2) {
        int2 e0 = g_sw[st + j];
        int2 e1 = g_sw[st + j + 1];
        float4 v0 = Sp[(size_t)e0.x * 16 + l];
        float4 v1 = Sp[(size_t)e1.x * 16 + l];
        float w0 = __int_as_float(e0.y);
        float w1 = __int_as_float(e1.y);
        ax += w0 * v0.x + w1 * v1.x;
        ay += w0 * v0.y + w1 * v1.y;
        az += w0 * v0.z + w1 * v1.z;
        aw += w0 * v0.w + w1 * v1.w;
    }
    if (j < cnt) {
        int2 e0 = g_sw[st + j];
        float4 v0 = Sp[(size_t)e0.x * 16 + l];
        float w0 = __int_as_float(e0.y);
        ax += w0 * v0.x; ay += w0 * v0.y; az += w0 * v0.z; aw += w0 * v0.w;
    }

    if (HOP2) {
        float4 b = ((const float4*)bias)[l];
        ax = 1.0f / (1.0f + __expf(-(ax + b.x)));
        ay = 1.0f / (1.0f + __expf(-(ay + b.y)));
        az = 1.0f / (1.0f + __expf(-(az + b.z)));
        aw = 1.0f / (1.0f + __expf(-(aw + b.w)));
        ((float4*)out)[(size_t)node * 16 + l] = make_float4(ax, ay, az, aw);
    } else {
        ((float4*)g_B)[(size_t)node * 16 + l] = make_float4(ax, ay, az, aw);
    }
}

// ---------------------------------------------------------------- launch
extern "C" void kernel_launch(void* const* d_in, const int* in_sizes, int n_in,
                              void* d_out, int out_size) {
    const float* x    = (const float*)d_in[0];
    const int*   ei32 = (const int*)d_in[1];   // raw words; dtype detected on device
    const float* W    = (const float*)d_in[2];
    const float* b    = (const float*)d_in[3];
    float*       out  = (float*)d_out;

    k_init      <<<(NN + 255) / 256, 256>>>(ei32);
    k_count     <<<(NE + 255) / 256, 256>>>(ei32);
    k_scan_local<<<NB, 256>>>();
    k_scan_tops <<<1, 128>>>();
    k_finalize  <<<(NN + 255) / 256, 256>>>();
    k_fill      <<<(NE + 255) / 256, 256>>>(ei32);

    k_gemm      <<<(NN + TNODE - 1) / TNODE, 256>>>(x, W);

    // hop 1: g_B = P * g_A          (warps = NN/2, 2 nodes per warp)
    k_gather<false><<<(NN / 2 * 32 + 255) / 256, 256>>>(nullptr, nullptr);
    // hop 2 + bias + sigmoid: out = sigmoid(P * g_B + b)
    k_gather<true> <<<(NN / 2 * 32 + 255) / 256, 256>>>(out, b);
}

// round 12
// speedup vs baseline: 1.2502x; 1.1760x over previous
#include <cuda_runtime.h>

#define NN 100000
#define NE 800000
#define IC 96
#define OC 64
#define GN 64             // nodes per GEMM block
#define CHUNK 1024        // scan chunk
#define NB ((NN + CHUNK - 1) / CHUNK)   // 98
static_assert(NB <= 128, "scan_tops assumes <=128 chunks");

// ---- scratch (static device globals; no allocation allowed) ----
// Referenced only from device code; never passed as kernel arguments.
__device__ int   g_is64;               // 1 if edge_index is int64, else int32
__device__ float g_dinv[NN];
__device__ int   g_cnt[NN];
__device__ int   g_rowstart[NN];
__device__ int   g_cursor[NN];
__device__ int   g_csum[128];
__device__ int   g_ctop[128];
__device__ __align__(16) int2  g_sw[NE];       // CSR-by-dest: (src, weight-bits)
__device__ __align__(16) float g_A[NN * OC];   // h = x W^T, hop-1 source
__device__ __align__(16) float g_B[NN * OC];   // hop-1 result / hop-2 source

// ---------------------------------------------------------------- edge fetch helper
__device__ __forceinline__ void load_edge(const int* p32, int e, int& r, int& c) {
    if (g_is64) {
        r = p32[2 * e];
        c = p32[2 * (NE + e)];
    } else {
        r = p32[e];
        c = p32[NE + e];
    }
}

// ---------------------------------------------------------------- init + dtype detect (fused)
__global__ void k_init(const int* __restrict__ ei32) {
    int i = blockIdx.x * blockDim.x + threadIdx.x;
    if (i < NN) g_cnt[i] = 0;
    if (i == 0) {
        int nz = 0;
        #pragma unroll 8
        for (int k = 0; k < 64; k++) nz |= ei32[2 * k + 1];
        g_is64 = (nz == 0) ? 1 : 0;   // odd int32 words all zero => int64 data
    }
}

// ---------------------------------------------------------------- count in-degree
__global__ void k_count(const int* __restrict__ ei32) {
    int e = blockIdx.x * blockDim.x + threadIdx.x;
    if (e < NE) {
        int r, c;
        load_edge(ei32, e, r, c);
        if ((unsigned)c < NN) atomicAdd(&g_cnt[c], 1);
    }
}

// ---------------------------------------------------------------- scan (1/3): per-chunk scan + dinv (fused)
__global__ void k_scan_local() {
    __shared__ int s[256];
    int t = threadIdx.x, blk = blockIdx.x;
    int base = blk * CHUNK + t * 4;
    int v0 = (base + 0 < NN) ? g_cnt[base + 0] : 0;
    int v1 = (base + 1 < NN) ? g_cnt[base + 1] : 0;
    int v2 = (base + 2 < NN) ? g_cnt[base + 2] : 0;
    int v3 = (base + 3 < NN) ? g_cnt[base + 3] : 0;
    // dinv while cnt is hot (deg includes +1 self loop)
    if (base + 0 < NN) g_dinv[base + 0] = rsqrtf((float)v0 + 1.0f);
    if (base + 1 < NN) g_dinv[base + 1] = rsqrtf((float)v1 + 1.0f);
    if (base + 2 < NN) g_dinv[base + 2] = rsqrtf((float)v2 + 1.0f);
    if (base + 3 < NN) g_dinv[base + 3] = rsqrtf((float)v3 + 1.0f);
    int sum = v0 + v1 + v2 + v3;
    s[t] = sum;
    __syncthreads();
    for (int off = 1; off < 256; off <<= 1) {
        int add = (t >= off) ? s[t - off] : 0;
        __syncthreads();
        s[t] += add;
        __syncthreads();
    }
    int excl = s[t] - sum;
    if (base + 0 < NN) g_rowstart[base + 0] = excl;
    if (base + 1 < NN) g_rowstart[base + 1] = excl + v0;
    if (base + 2 < NN) g_rowstart[base + 2] = excl + v0 + v1;
    if (base + 3 < NN) g_rowstart[base + 3] = excl + v0 + v1 + v2;
    if (t == 255) g_csum[blk] = s[255];
}

// ---------------------------------------------------------------- scan (2/3): chunk totals
__global__ void k_scan_tops() {
    __shared__ int s[128];
    int t = threadIdx.x;
    int v = (t < NB) ? g_csum[t] : 0;
    s[t] = v;
    __syncthreads();
    for (int off = 1; off < 128; off <<= 1) {
        int add = (t >= off) ? s[t - off] : 0;
        __syncthreads();
        s[t] += add;
        __syncthreads();
    }
    if (t < NB) g_ctop[t] = s[t] - v;   // exclusive
}

// ---------------------------------------------------------------- scan (3/3): finalize rowstart/cursor
__global__ void k_finalize() {
    int i = blockIdx.x * blockDim.x + threadIdx.x;
    if (i < NN) {
        int rs = g_rowstart[i] + g_ctop[i >> 10];
        g_rowstart[i] = rs;
        g_cursor[i]   = rs;
    }
}

// ---------------------------------------------------------------- CSR fill: packed (src, weight)
__global__ void k_fill(const int* __restrict__ ei32) {
    int e = blockIdx.x * blockDim.x + threadIdx.x;
    if (e < NE) {
        int r, c;
        load_edge(ei32, e, r, c);
        if ((unsigned)r < NN && (unsigned)c < NN) {
            int pos = atomicAdd(&g_cursor[c], 1);
            float w = g_dinv[r] * g_dinv[c];
            g_sw[pos] = make_int2(r, __float_as_int(w));
        }
    }
}

// ---------------------------------------------------------------- GEMM: g_A = x W^T
// 64 nodes x 64 oc per block, 256 threads, each thread 4n x 4oc (16 acc).
__global__ void __launch_bounds__(256) k_gemm(const float* __restrict__ x,
                                              const float* __restrict__ W) {
    __shared__ float Ws[IC][OC + 4];    // [96][68] padded
    __shared__ float xs[GN][IC + 4];    // [64][100] padded (row stride 400B, 16B-aligned)
    int tid = threadIdx.x;
    int b0  = blockIdx.x * GN;

    for (int i = tid; i < OC * IC; i += 256) {      // W[oc][k] -> Ws[k][oc]
        int oc = i / IC, k = i % IC;
        Ws[k][oc] = W[i];
    }
    // x tile, float4 loads (IC=96 -> 24 quads/row)
    for (int i = tid; i < GN * (IC / 4); i += 256) {
        int n = i / (IC / 4), q = i % (IC / 4);
        int gn = b0 + n;
        float4 v = (gn < NN) ? ((const float4*)x)[(size_t)gn * (IC / 4) + q]
                             : make_float4(0.f, 0.f, 0.f, 0.f);
        *(float4*)&xs[n][q * 4] = v;
    }
    __syncthreads();

    int ocq = (tid & 15) * 4;      // oc quad base
    int n0  = (tid >> 4) * 4;      // node quad base
    float acc[4][4] = {};

    #pragma unroll 8
    for (int k = 0; k < IC; k++) {
        float4 w = *(const float4*)&Ws[k][ocq];
        #pragma unroll
        for (int i = 0; i < 4; i++) {
            float xv = xs[n0 + i][k];
            acc[i][0] += xv * w.x; acc[i][1] += xv * w.y;
            acc[i][2] += xv * w.z; acc[i][3] += xv * w.w;
        }
    }

    #pragma unroll
    for (int i = 0; i < 4; i++) {
        int gn = b0 + n0 + i;
        if (gn < NN)
            *(float4*)&g_A[(size_t)gn * OC + ocq] =
                make_float4(acc[i][0], acc[i][1], acc[i][2], acc[i][3]);
    }
}

// ---------------------------------------------------------------- gather hops
// 2 nodes per warp (half-warp of 16 lanes x float4 = full 256B row per node).
// Unroll-4: 4 edge chains in flight per node => MLP ~8 per warp.
// D[d] = dinv[d]^2 * S[d] + sum_{e: col=d} w_e * S[src_e]
// HOP2=false: S=g_A, D=g_B. HOP2=true: S=g_B, D=out with bias+sigmoid.
template <bool HOP2>
__global__ void k_gather(float* __restrict__ out, const float* __restrict__ bias) {
    int warp = (blockIdx.x * blockDim.x + threadIdx.x) >> 5;
    int node = (warp << 1) | ((threadIdx.x >> 4) & 1);
    if (node >= NN) return;
    int l = threadIdx.x & 15;

    const float4* __restrict__ Sp = (const float4*)(HOP2 ? g_B : g_A);
    float dd = g_dinv[node]; dd *= dd;
    float4 a = Sp[(size_t)node * 16 + l];
    float ax = a.x * dd, ay = a.y * dd, az = a.z * dd, aw = a.w * dd;

    int st  = g_rowstart[node];
    int cnt = g_cnt[node];
    int j = 0;
    for (; j + 4 <= cnt; j += 4) {
        int2 e0 = g_sw[st + j];
        int2 e1 = g_sw[st + j + 1];
        int2 e2 = g_sw[st + j + 2];
        int2 e3 = g_sw[st + j + 3];
        float4 v0 = Sp[(size_t)e0.x * 16 + l];
        float4 v1 = Sp[(size_t)e1.x * 16 + l];
        float4 v2 = Sp[(size_t)e2.x * 16 + l];
        float4 v3 = Sp[(size_t)e3.x * 16 + l];
        float w0 = __int_as_float(e0.y), w1 = __int_as_float(e1.y);
        float w2 = __int_as_float(e2.y), w3 = __int_as_float(e3.y);
        ax += w0 * v0.x + w1 * v1.x + w2 * v2.x + w3 * v3.x;
        ay += w0 * v0.y + w1 * v1.y + w2 * v2.y + w3 * v3.y;
        az += w0 * v0.z + w1 * v1.z + w2 * v2.z + w3 * v3.z;
        aw += w0 * v0.w + w1 * v1.w + w2 * v2.w + w3 * v3.w;
    }
    for (; j < cnt; j++) {
        int2 e0 = g_sw[st + j];
        float4 v0 = Sp[(size_t)e0.x * 16 + l];
        float w0 = __int_as_float(e0.y);
        ax += w0 * v0.x; ay += w0 * v0.y; az += w0 * v0.z; aw += w0 * v0.w;
    }

    if (HOP2) {
        float4 b = ((const float4*)bias)[l];
        ax = 1.0f / (1.0f + __expf(-(ax + b.x)));
        ay = 1.0f / (1.0f + __expf(-(ay + b.y)));
        az = 1.0f / (1.0f + __expf(-(az + b.z)));
        aw = 1.0f / (1.0f + __expf(-(aw + b.w)));
        ((float4*)out)[(size_t)node * 16 + l] = make_float4(ax, ay, az, aw);
    } else {
        ((float4*)g_B)[(size_t)node * 16 + l] = make_float4(ax, ay, az, aw);
    }
}

// ---------------------------------------------------------------- launch
extern "C" void kernel_launch(void* const* d_in, const int* in_sizes, int n_in,
                              void* d_out, int out_size) {
    const float* x    = (const float*)d_in[0];
    const int*   ei32 = (const int*)d_in[1];   // raw words; dtype detected on device
    const float* W    = (const float*)d_in[2];
    const float* b    = (const float*)d_in[3];
    float*       out  = (float*)d_out;

    k_init      <<<(NN + 255) / 256, 256>>>(ei32);
    k_count     <<<(NE + 255) / 256, 256>>>(ei32);
    k_scan_local<<<NB, 256>>>();
    k_scan_tops <<<1, 128>>>();
    k_finalize  <<<(NN + 255) / 256, 256>>>();
    k_fill      <<<(NE + 255) / 256, 256>>>(ei32);

    k_gemm      <<<(NN + GN - 1) / GN, 256>>>(x, W);

    // hop 1: g_B = P * g_A          (2 nodes per warp)
    k_gather<false><<<(NN / 2 * 32 + 255) / 256, 256>>>(nullptr, nullptr);
    // hop 2 + bias + sigmoid: out = sigmoid(P * g_B + b)
    k_gather<true> <<<(NN / 2 * 32 + 255) / 256, 256>>>(out, b);
}